// round 8
// baseline (speedup 1.0000x reference)
#include <cuda_runtime.h>
#include <cuda_fp16.h>
#include <cstdint>

#define NB 16
#define NT 4096
#define NH 512
#define TM 128      // t-rows per pair-tile
#define KC 64       // k per chunk (8 chunks)

// ---------------- device scratch ----------------
__device__ __half g_wv[NH * NH];                // Wv in fp16, [o][h]
__device__ float  g_qbb[NB * NH];               // q@Wq + bias + conv_b
__device__ float  g_score[NB * NT];             // partial scores (atomic, 2 adds each)
__device__ int    g_cnt[NB * (NT / TM)];        // per pair-tile arrival counter
__device__ float  g_sig[NB * NT];               // unnormalized sigmoid
__device__ float  g_sum[NB];                    // per-batch sum of sig
__device__ float  g_ctx[NB * NH];               // unnormalized context

// ---------------- helpers ----------------
static __device__ __forceinline__ uint32_t s2u(const void* p) {
    uint32_t a;
    asm("{ .reg .u64 t; cvta.to.shared.u64 t, %1; cvt.u32.u64 %0, t; }" : "=r"(a) : "l"(p));
    return a;
}
static __device__ __forceinline__ void cp16(uint32_t dst, const void* src) {
    asm volatile("cp.async.cg.shared.global [%0], [%1], 16;" :: "r"(dst), "l"(src));
}
#define CP_COMMIT() asm volatile("cp.async.commit_group;" ::: "memory")
#define CP_WAIT0()  asm volatile("cp.async.wait_group 0;" ::: "memory")

static __device__ __forceinline__ void ldsm4(uint32_t* r, uint32_t addr) {
    asm volatile("ldmatrix.sync.aligned.m8n8.x4.shared.b16 {%0,%1,%2,%3}, [%4];"
                 : "=r"(r[0]), "=r"(r[1]), "=r"(r[2]), "=r"(r[3]) : "r"(addr));
}
static __device__ __forceinline__ void mma16816(float* c, const uint32_t* a, const uint32_t* b) {
    asm volatile("mma.sync.aligned.m16n8k16.row.col.f32.f16.f16.f32 "
                 "{%0,%1,%2,%3}, {%4,%5,%6,%7}, {%8,%9}, {%0,%1,%2,%3};"
                 : "+f"(c[0]), "+f"(c[1]), "+f"(c[2]), "+f"(c[3])
                 : "r"(a[0]), "r"(a[1]), "r"(a[2]), "r"(a[3]), "r"(b[0]), "r"(b[1]));
}
static __device__ __forceinline__ float tanh_fast(float x) {
    float y; asm("tanh.approx.f32 %0, %1;" : "=f"(y) : "f"(x)); return y;
}

// ---------------- smem layout (bytes) ----------------
#define SA    0                        // 8 chunks x (128x64 fp16 = 16384) = 131072, resident
#define SB    131072                   // 2 buffers x (256x64 fp16 = 32768) = 65536
#define SQ    196608                   // qbb   256 f (this CTA's half)
#define SC0   197632
#define SC1   198656
#define SC2   199680
#define SWS   200704
#define SLA   201728                   // 130 f (pad 1024)
#define SROW  202752                   // 128 f
#define SSIG  203264                   // 128 f
#define SMEM_MAIN 203776

// ================= k_prep: qbb; Wv->fp16; zero accum/score/cnt =================
__global__ void k_prep(const float* __restrict__ query, const float* __restrict__ Wq,
                       const float* __restrict__ bias, const float* __restrict__ conv_b,
                       const float* __restrict__ Wv) {
    int b = blockIdx.y, og = blockIdx.x;
    int w = threadIdx.x >> 5, lane = threadIdx.x & 31;
    int o = og * 8 + w;
    const float* qr = query + b * NH;
    const float* wr = Wq + o * NH;
    float s = 0.f;
    #pragma unroll 4
    for (int j = lane; j < NH; j += 32) s += qr[j] * wr[j];
    #pragma unroll
    for (int off = 16; off; off >>= 1) s += __shfl_xor_sync(0xffffffffu, s, off);
    if (lane == 0) g_qbb[b * NH + o] = s + bias[o] + conv_b[o];

    int flat = (blockIdx.y * 64 + blockIdx.x) * 256 + threadIdx.x;   // 0..262143
    if (flat < NH * NH / 4) {                       // 65536 float4s of Wv
        float4 v = ((const float4*)Wv)[flat];
        union { __half2 h[2]; uint2 u; } cv;
        cv.h[0] = __floats2half2_rn(v.x, v.y);
        cv.h[1] = __floats2half2_rn(v.z, v.w);
        ((uint2*)g_wv)[flat] = cv.u;
    }
    g_score[flat] = 0.f;                            // NB*NT == 262144 exactly
    if (flat < NB * NH) g_ctx[flat] = 0.f;
    if (flat < NB * (NT / TM)) g_cnt[flat] = 0;
    if (flat < NB) g_sum[flat] = 0.f;
}

// ================= k_main: pair-split fused GEMM + stitched epilogue =================
__global__ __launch_bounds__(256, 1)
void k_main(const float* __restrict__ value, const float* __restrict__ conv_w,
            const float* __restrict__ w_score, const float* __restrict__ last_attn,
            const float* __restrict__ b_score) {
    extern __shared__ char smem[];
    const int tid = threadIdx.x;
    const int b = blockIdx.y;
    const int pairIdx = blockIdx.x >> 1;            // 0..31
    const int half = blockIdx.x & 1;                // N-half: cols [half*256, +256)
    const int t0 = pairIdx * TM;
    const int o0 = half * 256;
    const uint32_t sb = s2u(smem);

    float* s_qbb = (float*)(smem + SQ);
    float* s_c0  = (float*)(smem + SC0);
    float* s_c1  = (float*)(smem + SC1);
    float* s_c2  = (float*)(smem + SC2);
    float* s_ws  = (float*)(smem + SWS);
    float* s_la  = (float*)(smem + SLA);
    float* s_row = (float*)(smem + SROW);
    float* s_sig = (float*)(smem + SSIG);

    if (tid < 256) {
        int o = o0 + tid;
        s_qbb[tid] = g_qbb[b * NH + o];
        s_c0[tid]  = conv_w[o * 3 + 0];
        s_c1[tid]  = conv_w[o * 3 + 1];
        s_c2[tid]  = conv_w[o * 3 + 2];
        s_ws[tid]  = w_score[o];
    }
    if (tid < TM + 2) {
        int g = t0 - 1 + tid;
        s_la[tid] = (g >= 0 && g < NT) ? last_attn[b * NT + g] : 0.f;
    }
    if (tid < TM) s_row[tid] = 0.f;

    const float* vrow = value + ((size_t)(b * NT + t0)) * NH;

    // A chunk: fp32 -> fp16 swizzled; 4 x 16B units per thread (128 rows x 8 units)
    auto loadA = [&](int kc) {
        #pragma unroll
        for (int j = 0; j < 4; j++) {
            int e = tid + 256 * j;                  // 0..1023 units
            int r = e >> 3, u = e & 7;
            const float4* src = (const float4*)(vrow + (size_t)r * NH + kc * KC + u * 8);
            float4 x = src[0], y = src[1];
            __half2 h0 = __floats2half2_rn(x.x, x.y);
            __half2 h1 = __floats2half2_rn(x.z, x.w);
            __half2 h2 = __floats2half2_rn(y.x, y.y);
            __half2 h3 = __floats2half2_rn(y.z, y.w);
            uint4 pk;
            pk.x = *(uint32_t*)&h0; pk.y = *(uint32_t*)&h1;
            pk.z = *(uint32_t*)&h2; pk.w = *(uint32_t*)&h3;
            *(uint4*)(smem + SA + kc * 16384 + r * 128 + ((u ^ (r & 7)) << 4)) = pk;
        }
    };
    // B chunk: cp.async fp16, this CTA's 256 rows (8 units per thread)
    auto issueB = [&](int kc, int buf) {
        uint32_t bb = sb + SB + buf * 32768;
        #pragma unroll
        for (int j = 0; j < 8; j++) {
            int e = tid + 256 * j;                  // 0..2047 units
            int r = e >> 3, u = e & 7;
            cp16(bb + r * 128 + ((u ^ (r & 7)) << 4),
                 g_wv + (size_t)(o0 + r) * NH + kc * KC + u * 8);
        }
    };

    issueB(0, 0); CP_COMMIT();
    loadA(0); loadA(1);

    // warp tiling: 2(M) x 4(N) warps; warp tile M=64 x N=64
    const int w = tid >> 5, l = tid & 31;
    const int wm = w >> 2, wn = w & 3;
    const int i3 = l >> 3;
    const int arow_base = wm * 64 + ((i3 & 1) << 3) + (l & 7);   // + mt*16
    const int aku  = i3 >> 1;
    const int brow_base = wn * 64 + ((i3 >> 1) << 3) + (l & 7);  // + p*16
    const int bku  = i3 & 1;

    float acc[4][8][4];
    #pragma unroll
    for (int mt = 0; mt < 4; mt++)
        #pragma unroll
        for (int nt = 0; nt < 8; nt++)
            #pragma unroll
            for (int e = 0; e < 4; e++) acc[mt][nt][e] = 0.f;

    for (int kc = 0; kc < 8; kc++) {
        // prefetch A(kc+2): LDG + convert to packed fp16 regs (16 regs) before B wait
        uint4 pa[4];
        if (kc < 6) {
            #pragma unroll
            for (int j = 0; j < 4; j++) {
                int e = tid + 256 * j;
                int r = e >> 3, u = e & 7;
                const float4* src = (const float4*)(vrow + (size_t)r * NH + (kc + 2) * KC + u * 8);
                float4 x = src[0], y = src[1];
                __half2 h0 = __floats2half2_rn(x.x, x.y);
                __half2 h1 = __floats2half2_rn(x.z, x.w);
                __half2 h2 = __floats2half2_rn(y.x, y.y);
                __half2 h3 = __floats2half2_rn(y.z, y.w);
                pa[j].x = *(uint32_t*)&h0; pa[j].y = *(uint32_t*)&h1;
                pa[j].z = *(uint32_t*)&h2; pa[j].w = *(uint32_t*)&h3;
            }
        }

        CP_WAIT0();             // B(kc) landed
        __syncthreads();        // prior-iter B reads done; A(kc) stores visible

        if (kc < 7) { issueB(kc + 1, (kc + 1) & 1); CP_COMMIT(); }

        uint32_t ab = sb + SA + kc * 16384;
        uint32_t bb = sb + SB + (kc & 1) * 32768;
        #pragma unroll
        for (int s = 0; s < 4; s++) {
            uint32_t af[4][4];
            uint32_t au = (2 * s + aku);
            #pragma unroll
            for (int mt = 0; mt < 4; mt++) {
                int r = arow_base + mt * 16;
                ldsm4(af[mt], ab + r * 128 + ((au ^ (r & 7)) << 4));
            }
            uint32_t bf[8][2];
            uint32_t bu = (2 * s + bku);
            #pragma unroll
            for (int p = 0; p < 4; p++) {
                int r = brow_base + p * 16;
                uint32_t t4[4];
                ldsm4(t4, bb + r * 128 + ((bu ^ (r & 7)) << 4));
                bf[2 * p][0] = t4[0]; bf[2 * p][1] = t4[1];
                bf[2 * p + 1][0] = t4[2]; bf[2 * p + 1][1] = t4[3];
            }
            #pragma unroll
            for (int mt = 0; mt < 4; mt++)
                #pragma unroll
                for (int nt = 0; nt < 8; nt++)
                    mma16816(acc[mt][nt], af[mt], bf[nt]);
        }

        if (kc < 6) {
            #pragma unroll
            for (int j = 0; j < 4; j++) {
                int e = tid + 256 * j;
                int r = e >> 3, u = e & 7;
                *(uint4*)(smem + SA + (kc + 2) * 16384 + r * 128 + ((u ^ (r & 7)) << 4)) = pa[j];
            }
        }
        // next iteration's top sync protects buffers
    }

    // ---- epilogue 1: partial score over this CTA's 256 cols ----
    {
        float lam[8], lb_[8], lc_[8];
        #pragma unroll
        for (int mt = 0; mt < 4; mt++)
            #pragma unroll
            for (int e = 0; e < 2; e++) {
                int r = wm * 64 + mt * 16 + (l >> 2) + 8 * e;
                int ri = mt * 2 + e;
                lam[ri] = s_la[r]; lb_[ri] = s_la[r + 1]; lc_[ri] = s_la[r + 2];
            }
        float rs[8] = {0.f, 0.f, 0.f, 0.f, 0.f, 0.f, 0.f, 0.f};
        #pragma unroll
        for (int nt = 0; nt < 8; nt++) {
            int c = wn * 64 + nt * 8 + 2 * (l & 3);     // local col in [0,256)
            float qb0 = s_qbb[c], qb1 = s_qbb[c + 1];
            float c00 = s_c0[c],  c01 = s_c0[c + 1];
            float c10 = s_c1[c],  c11 = s_c1[c + 1];
            float c20 = s_c2[c],  c21 = s_c2[c + 1];
            float ws0 = s_ws[c],  ws1 = s_ws[c + 1];
            #pragma unroll
            for (int mt = 0; mt < 4; mt++)
                #pragma unroll
                for (int e = 0; e < 2; e++) {
                    int ri = mt * 2 + e;
                    float x0 = acc[mt][nt][2 * e + 0] + qb0 + lam[ri] * c00 + lb_[ri] * c10 + lc_[ri] * c20;
                    float x1 = acc[mt][nt][2 * e + 1] + qb1 + lam[ri] * c01 + lb_[ri] * c11 + lc_[ri] * c21;
                    rs[ri] += ws0 * tanh_fast(x0) + ws1 * tanh_fast(x1);
                }
        }
        #pragma unroll
        for (int ri = 0; ri < 8; ri++) {
            rs[ri] += __shfl_xor_sync(0xffffffffu, rs[ri], 1);
            rs[ri] += __shfl_xor_sync(0xffffffffu, rs[ri], 2);
        }
        if ((l & 3) == 0) {
            #pragma unroll
            for (int mt = 0; mt < 4; mt++)
                #pragma unroll
                for (int e = 0; e < 2; e++)
                    atomicAdd(&s_row[wm * 64 + mt * 16 + (l >> 2) + 8 * e], rs[mt * 2 + e]);
        }
    }
    __syncthreads();

    // publish partial score, then pair-arrival protocol
    if (tid < TM) atomicAdd(&g_score[b * NT + t0 + tid], s_row[tid]);
    __threadfence();
    __syncthreads();
    __shared__ int slast;
    if (tid == 0) slast = (atomicAdd(&g_cnt[b * (NT / TM) + pairIdx], 1) == 1);
    __syncthreads();

    if (slast) {
        __threadfence();        // acquire side: peer's score adds visible
        // ---- epilogue 2: sigmoid + batch-sum (full score now assembled) ----
        if (tid < TM) {
            float sg = 1.f / (1.f + __expf(-(g_score[b * NT + t0 + tid] + b_score[0])));
            s_sig[tid] = sg;
            g_sig[b * NT + t0 + tid] = sg;
            float s = sg;
            #pragma unroll
            for (int off = 16; off; off >>= 1) s += __shfl_xor_sync(0xffffffffu, s, off);
            if ((tid & 31) == 0) atomicAdd(&g_sum[b], s);
        }
        __syncthreads();

        // ---- epilogue 3: full context from resident fp16 A (all 512 h) ----
        {
            int kc = tid >> 5, j2 = tid & 31;       // half2 col: h = 2*tid
            const char* base = smem + SA + kc * 16384;
            float a0 = 0.f, a1 = 0.f;
            #pragma unroll 16
            for (int t = 0; t < TM; t++) {
                uint32_t off = (uint32_t)t * 128 + ((((j2 >> 2) ^ (t & 7)) << 4) + (j2 & 3) * 4);
                __half2 hv = *(const __half2*)(base + off);
                float2 fv = __half22float2(hv);
                float wgt = s_sig[t];
                a0 = fmaf(wgt, fv.x, a0);
                a1 = fmaf(wgt, fv.y, a1);
            }
            atomicAdd(&g_ctx[b * NH + 2 * tid + 0], a0);
            atomicAdd(&g_ctx[b * NH + 2 * tid + 1], a1);
        }
    }
}

// ================= k_fin: normalize + assemble out =================
__global__ void k_fin(const float* __restrict__ query, float* __restrict__ out) {
    int idx = blockIdx.x * 256 + threadIdx.x;       // 81920
    if (idx < NB * 2 * NH) {
        int b = idx >> 10, c = idx & 1023;
        out[idx] = (c < NH) ? g_ctx[b * NH + c] / g_sum[b] : query[b * NH + (c - NH)];
    } else {
        int i = idx - NB * 2 * NH;
        int b = i >> 12;
        out[idx] = g_sig[i] / g_sum[b];
    }
}

// ================= launch =================
extern "C" void kernel_launch(void* const* d_in, const int* in_sizes, int n_in,
                              void* d_out, int out_size) {
    (void)in_sizes; (void)n_in; (void)out_size;
    const float* query     = (const float*)d_in[0];
    const float* value     = (const float*)d_in[1];
    const float* last_attn = (const float*)d_in[2];
    const float* conv_w    = (const float*)d_in[3];
    const float* conv_b    = (const float*)d_in[4];
    const float* Wq        = (const float*)d_in[5];
    const float* Wv        = (const float*)d_in[6];
    const float* bias      = (const float*)d_in[7];
    const float* w_score   = (const float*)d_in[8];
    const float* b_score   = (const float*)d_in[9];
    float* out = (float*)d_out;

    static int smem_set = 0;
    if (!smem_set) {
        cudaFuncSetAttribute(k_main, cudaFuncAttributeMaxDynamicSharedMemorySize, SMEM_MAIN);
        smem_set = 1;
    }

    k_prep<<<dim3(64, 16), 256>>>(query, Wq, bias, conv_b, Wv);
    k_main<<<dim3(64, 16), 256, SMEM_MAIN>>>(value, conv_w, w_score, last_attn, b_score);
    k_fin <<<320, 256>>>(query, out);
}

// round 9
// speedup vs baseline: 1.3501x; 1.3501x over previous
#include <cuda_runtime.h>
#include <cuda_fp16.h>
#include <cstdint>

#define NB 16
#define NT 4096
#define NH 512
#define TM 64       // t-rows per tile
#define KC 64       // k per chunk (8 chunks)

// ---------------- device scratch ----------------
__device__ __half g_wv[NH * NH];                // Wv in fp16, [o][h]
__device__ float  g_qbb[NB * NH];               // q@Wq + bias + conv_b
__device__ float  g_sig[NB * NT];               // unnormalized sigmoid
__device__ float  g_sum[NB];                    // per-batch sum of sig
__device__ float  g_ctx[NB * NH];               // unnormalized context

// ---------------- helpers ----------------
static __device__ __forceinline__ uint32_t s2u(const void* p) {
    uint32_t a;
    asm("{ .reg .u64 t; cvta.to.shared.u64 t, %1; cvt.u32.u64 %0, t; }" : "=r"(a) : "l"(p));
    return a;
}
static __device__ __forceinline__ void cp16(uint32_t dst, const void* src) {
    asm volatile("cp.async.cg.shared.global [%0], [%1], 16;" :: "r"(dst), "l"(src));
}
#define CP_COMMIT() asm volatile("cp.async.commit_group;" ::: "memory")
#define CP_WAIT0()  asm volatile("cp.async.wait_group 0;" ::: "memory")

static __device__ __forceinline__ void ldsm4(uint32_t* r, uint32_t addr) {
    asm volatile("ldmatrix.sync.aligned.m8n8.x4.shared.b16 {%0,%1,%2,%3}, [%4];"
                 : "=r"(r[0]), "=r"(r[1]), "=r"(r[2]), "=r"(r[3]) : "r"(addr));
}
static __device__ __forceinline__ void mma16816(float* c, const uint32_t* a, const uint32_t* b) {
    asm volatile("mma.sync.aligned.m16n8k16.row.col.f32.f16.f16.f32 "
                 "{%0,%1,%2,%3}, {%4,%5,%6,%7}, {%8,%9}, {%0,%1,%2,%3};"
                 : "+f"(c[0]), "+f"(c[1]), "+f"(c[2]), "+f"(c[3])
                 : "r"(a[0]), "r"(a[1]), "r"(a[2]), "r"(a[3]), "r"(b[0]), "r"(b[1]));
}
static __device__ __forceinline__ float tanh_fast(float x) {
    float y; asm("tanh.approx.f32 %0, %1;" : "=f"(y) : "f"(x)); return y;
}

// ---------------- smem layout (bytes) ----------------
#define SA    0                        // 8 chunks x (64x64 fp16 = 8192) = 65536, resident
#define SB    65536                    // 2 buffers x (512x64 fp16 = 65536) = 131072
#define SQ    196608                   // qbb 512 f
#define SC0   198656
#define SC1   200704
#define SC2   202752
#define SWS   204800
#define SLA   206848                   // 66 f (pad)
#define SROW  207872                   // 64 f
#define SSIG  208128                   // 64 f
#define SMEM_MAIN 208384

// ================= k_prep (R6 form, measured 6.3 µs): qbb; Wv->fp16; zero =================
__global__ void k_prep(const float* __restrict__ query, const float* __restrict__ Wq,
                       const float* __restrict__ bias, const float* __restrict__ conv_b,
                       const float* __restrict__ Wv) {
    int b = blockIdx.y, og = blockIdx.x;
    int w = threadIdx.x >> 5, lane = threadIdx.x & 31;
    int o = og * 8 + w;
    const float* qr = query + b * NH;
    const float* wr = Wq + o * NH;
    float s = 0.f;
    #pragma unroll 4
    for (int j = lane; j < NH; j += 32) s += qr[j] * wr[j];
    #pragma unroll
    for (int off = 16; off; off >>= 1) s += __shfl_xor_sync(0xffffffffu, s, off);
    if (lane == 0) g_qbb[b * NH + o] = s + bias[o] + conv_b[o];

    int flat = (blockIdx.y * 64 + blockIdx.x) * 256 + threadIdx.x;   // 0..262143
    if (flat < NH * NH / 4) {                       // 65536 float4s of Wv
        float4 v = ((const float4*)Wv)[flat];
        union { __half2 h[2]; uint2 u; } cv;
        cv.h[0] = __floats2half2_rn(v.x, v.y);
        cv.h[1] = __floats2half2_rn(v.z, v.w);
        ((uint2*)g_wv)[flat] = cv.u;
    }
    if (flat < NB * NH) g_ctx[flat] = 0.f;
    if (flat < NB)      g_sum[flat] = 0.f;
}

// ================= k_main (R7 form): fused GEMM + epilogues, 1 barrier per chunk =================
__global__ __launch_bounds__(256, 1)
void k_main(const float* __restrict__ value, const float* __restrict__ conv_w,
            const float* __restrict__ w_score, const float* __restrict__ last_attn,
            const float* __restrict__ b_score) {
    extern __shared__ char smem[];
    const int tid = threadIdx.x;
    const int b = blockIdx.y;
    const int t0 = blockIdx.x * TM;
    const uint32_t sb = s2u(smem);

    float* s_qbb = (float*)(smem + SQ);
    float* s_c0  = (float*)(smem + SC0);
    float* s_c1  = (float*)(smem + SC1);
    float* s_c2  = (float*)(smem + SC2);
    float* s_ws  = (float*)(smem + SWS);
    float* s_la  = (float*)(smem + SLA);
    float* s_row = (float*)(smem + SROW);
    float* s_sig = (float*)(smem + SSIG);

    for (int i = tid; i < NH; i += 256) {
        s_qbb[i] = g_qbb[b * NH + i];
        s_c0[i]  = conv_w[i * 3 + 0];
        s_c1[i]  = conv_w[i * 3 + 1];
        s_c2[i]  = conv_w[i * 3 + 2];
        s_ws[i]  = w_score[i];
    }
    if (tid < TM + 2) {
        int g = t0 - 1 + tid;
        s_la[tid] = (g >= 0 && g < NT) ? last_attn[b * NT + g] : 0.f;
    }
    if (tid < TM) s_row[tid] = 0.f;

    const float* vrow = value + ((size_t)(b * NT + t0)) * NH;

    // A chunk: fp32 -> fp16 swizzled (2 x 16B units per thread)
    auto loadA = [&](int kc) {
        #pragma unroll
        for (int e0 = 0; e0 < 2; e0++) {
            int e = tid + 256 * e0;                 // 0..511 units
            int r = e >> 3, u = e & 7;
            const float4* src = (const float4*)(vrow + (size_t)r * NH + kc * KC + u * 8);
            float4 x = src[0], y = src[1];
            __half2 h0 = __floats2half2_rn(x.x, x.y);
            __half2 h1 = __floats2half2_rn(x.z, x.w);
            __half2 h2 = __floats2half2_rn(y.x, y.y);
            __half2 h3 = __floats2half2_rn(y.z, y.w);
            uint4 pk;
            pk.x = *(uint32_t*)&h0; pk.y = *(uint32_t*)&h1;
            pk.z = *(uint32_t*)&h2; pk.w = *(uint32_t*)&h3;
            *(uint4*)(smem + SA + kc * 8192 + r * 128 + ((u ^ (r & 7)) << 4)) = pk;
        }
    };
    // B chunk: cp.async fp16 (16 units per thread)
    auto issueB = [&](int kc, int buf) {
        uint32_t bb = sb + SB + buf * 65536;
        #pragma unroll
        for (int j = 0; j < 16; j++) {
            int idx = tid + 256 * j;                // 0..4095 units
            int r = idx >> 3, u = idx & 7;
            cp16(bb + r * 128 + ((u ^ (r & 7)) << 4),
                 g_wv + (size_t)r * NH + kc * KC + u * 8);
        }
    };

    issueB(0, 0); CP_COMMIT();
    loadA(0); loadA(1);

    // warp tiling: 8 warps side by side in N; warp tile M=64 x N=64
    const int w = tid >> 5, l = tid & 31;
    const int i3 = l >> 3;
    const int arow_base = ((i3 & 1) << 3) + (l & 7);            // + mt*16
    const int aku  = i3 >> 1;
    const int brow_base = w * 64 + ((i3 >> 1) << 3) + (l & 7);  // + p*16
    const int bku  = i3 & 1;

    float acc[4][8][4];
    #pragma unroll
    for (int mt = 0; mt < 4; mt++)
        #pragma unroll
        for (int nt = 0; nt < 8; nt++)
            #pragma unroll
            for (int e = 0; e < 4; e++) acc[mt][nt][e] = 0.f;

    for (int kc = 0; kc < 8; kc++) {
        // hoist A(kc+2) global loads above the B wait (no smem dependency)
        float4 px[2], py[2];
        if (kc < 6) {
            #pragma unroll
            for (int e0 = 0; e0 < 2; e0++) {
                int e = tid + 256 * e0;
                int r = e >> 3, u = e & 7;
                const float4* src = (const float4*)(vrow + (size_t)r * NH + (kc + 2) * KC + u * 8);
                px[e0] = src[0]; py[e0] = src[1];
            }
        }

        CP_WAIT0();             // B(kc) landed
        __syncthreads();        // prior-iter B reads done; A(kc) stores visible

        if (kc < 7) { issueB(kc + 1, (kc + 1) & 1); CP_COMMIT(); }

        uint32_t ab = sb + SA + kc * 8192;
        uint32_t bb = sb + SB + (kc & 1) * 65536;
        #pragma unroll
        for (int s = 0; s < 4; s++) {
            uint32_t af[4][4];
            uint32_t au = (2 * s + aku);
            #pragma unroll
            for (int mt = 0; mt < 4; mt++) {
                int r = arow_base + mt * 16;
                ldsm4(af[mt], ab + r * 128 + ((au ^ (r & 7)) << 4));
            }
            uint32_t bf[8][2];
            uint32_t bu = (2 * s + bku);
            #pragma unroll
            for (int p = 0; p < 4; p++) {
                int r = brow_base + p * 16;
                uint32_t t4[4];
                ldsm4(t4, bb + r * 128 + ((bu ^ (r & 7)) << 4));
                bf[2 * p][0] = t4[0]; bf[2 * p][1] = t4[1];
                bf[2 * p + 1][0] = t4[2]; bf[2 * p + 1][1] = t4[3];
            }
            #pragma unroll
            for (int mt = 0; mt < 4; mt++)
                #pragma unroll
                for (int nt = 0; nt < 8; nt++)
                    mma16816(acc[mt][nt], af[mt], bf[nt]);
        }

        if (kc < 6) {
            #pragma unroll
            for (int e0 = 0; e0 < 2; e0++) {
                int e = tid + 256 * e0;
                int r = e >> 3, u = e & 7;
                __half2 h0 = __floats2half2_rn(px[e0].x, px[e0].y);
                __half2 h1 = __floats2half2_rn(px[e0].z, px[e0].w);
                __half2 h2 = __floats2half2_rn(py[e0].x, py[e0].y);
                __half2 h3 = __floats2half2_rn(py[e0].z, py[e0].w);
                uint4 pk;
                pk.x = *(uint32_t*)&h0; pk.y = *(uint32_t*)&h1;
                pk.z = *(uint32_t*)&h2; pk.w = *(uint32_t*)&h3;
                *(uint4*)(smem + SA + (kc + 2) * 8192 + r * 128 + ((u ^ (r & 7)) << 4)) = pk;
            }
        }
        // no end-of-chunk barrier: next iteration's top sync covers buffer + A-chunk reuse
    }

    // ---- epilogue 1: score over this warp's 64 cols, all 64 rows ----
    {
        float lam[8], lb_[8], lc_[8];
        #pragma unroll
        for (int mt = 0; mt < 4; mt++)
            #pragma unroll
            for (int e = 0; e < 2; e++) {
                int r = mt * 16 + (l >> 2) + 8 * e;
                int ri = mt * 2 + e;
                lam[ri] = s_la[r]; lb_[ri] = s_la[r + 1]; lc_[ri] = s_la[r + 2];
            }
        float rs[8] = {0.f, 0.f, 0.f, 0.f, 0.f, 0.f, 0.f, 0.f};
        #pragma unroll
        for (int nt = 0; nt < 8; nt++) {
            int c = w * 64 + nt * 8 + 2 * (l & 3);
            float qb0 = s_qbb[c], qb1 = s_qbb[c + 1];
            float c00 = s_c0[c],  c01 = s_c0[c + 1];
            float c10 = s_c1[c],  c11 = s_c1[c + 1];
            float c20 = s_c2[c],  c21 = s_c2[c + 1];
            float ws0 = s_ws[c],  ws1 = s_ws[c + 1];
            #pragma unroll
            for (int mt = 0; mt < 4; mt++)
                #pragma unroll
                for (int e = 0; e < 2; e++) {
                    int ri = mt * 2 + e;
                    float x0 = acc[mt][nt][2 * e + 0] + qb0 + lam[ri] * c00 + lb_[ri] * c10 + lc_[ri] * c20;
                    float x1 = acc[mt][nt][2 * e + 1] + qb1 + lam[ri] * c01 + lb_[ri] * c11 + lc_[ri] * c21;
                    rs[ri] += ws0 * tanh_fast(x0) + ws1 * tanh_fast(x1);
                }
        }
        #pragma unroll
        for (int ri = 0; ri < 8; ri++) {
            rs[ri] += __shfl_xor_sync(0xffffffffu, rs[ri], 1);
            rs[ri] += __shfl_xor_sync(0xffffffffu, rs[ri], 2);
        }
        if ((l & 3) == 0) {
            #pragma unroll
            for (int mt = 0; mt < 4; mt++)
                #pragma unroll
                for (int e = 0; e < 2; e++)
                    atomicAdd(&s_row[mt * 16 + (l >> 2) + 8 * e], rs[mt * 2 + e]);
        }
    }
    __syncthreads();

    // ---- epilogue 2: sigmoid + batch-sum ----
    if (tid < TM) {
        float sg = 1.f / (1.f + __expf(-(s_row[tid] + b_score[0])));
        s_sig[tid] = sg;
        g_sig[b * NT + t0 + tid] = sg;
        float s = sg;
        #pragma unroll
        for (int off = 16; off; off >>= 1) s += __shfl_xor_sync(0xffffffffu, s, off);
        if ((tid & 31) == 0) atomicAdd(&g_sum[b], s);
    }
    __syncthreads();

    // ---- epilogue 3: partial context from resident fp16 A ----
    {
        int kc = tid >> 5, j2 = tid & 31;           // half2 col: h = 2*tid
        const char* base = smem + SA + kc * 8192;
        float a0 = 0.f, a1 = 0.f;
        #pragma unroll 16
        for (int t = 0; t < TM; t++) {
            uint32_t off = (uint32_t)t * 128 + ((((j2 >> 2) ^ (t & 7)) << 4) + (j2 & 3) * 4);
            __half2 hv = *(const __half2*)(base + off);
            float2 fv = __half22float2(hv);
            float wgt = s_sig[t];
            a0 = fmaf(wgt, fv.x, a0);
            a1 = fmaf(wgt, fv.y, a1);
        }
        atomicAdd(&g_ctx[b * NH + 2 * tid + 0], a0);
        atomicAdd(&g_ctx[b * NH + 2 * tid + 1], a1);
    }
}

// ================= k_fin: normalize + assemble out =================
__global__ void k_fin(const float* __restrict__ query, float* __restrict__ out) {
    int idx = blockIdx.x * 1024 + threadIdx.x;      // 81920
    if (idx < NB * 2 * NH) {
        int b = idx >> 10, c = idx & 1023;
        out[idx] = (c < NH) ? g_ctx[b * NH + c] / g_sum[b] : query[b * NH + (c - NH)];
    } else {
        int i = idx - NB * 2 * NH;
        int b = i >> 12;
        out[idx] = g_sig[i] / g_sum[b];
    }
}

// ================= launch =================
extern "C" void kernel_launch(void* const* d_in, const int* in_sizes, int n_in,
                              void* d_out, int out_size) {
    (void)in_sizes; (void)n_in; (void)out_size;
    const float* query     = (const float*)d_in[0];
    const float* value     = (const float*)d_in[1];
    const float* last_attn = (const float*)d_in[2];
    const float* conv_w    = (const float*)d_in[3];
    const float* conv_b    = (const float*)d_in[4];
    const float* Wq        = (const float*)d_in[5];
    const float* Wv        = (const float*)d_in[6];
    const float* bias      = (const float*)d_in[7];
    const float* w_score   = (const float*)d_in[8];
    const float* b_score   = (const float*)d_in[9];
    float* out = (float*)d_out;

    static int smem_set = 0;
    if (!smem_set) {
        cudaFuncSetAttribute(k_main, cudaFuncAttributeMaxDynamicSharedMemorySize, SMEM_MAIN);
        smem_set = 1;
    }

    k_prep<<<dim3(64, 16), 256>>>(query, Wq, bias, conv_b, Wv);
    k_main<<<dim3(NT / TM, NB), 256, SMEM_MAIN>>>(value, conv_w, w_score, last_attn, b_score);
    k_fin <<<80, 1024>>>(query, out);
}